// round 2
// baseline (speedup 1.0000x reference)
#include <cuda_runtime.h>
#include <cuda_bf16.h>
#include <cstdio>

#define NN 50000
#define EE 1000000
#define BB 512
#define HH 128
#define MID 64
#define IN1 54
#define IN2 18

// ---------------- scratch (no allocation allowed) ----------------
__device__ float g_xact[NN * HH];
__device__ float g_agg1[NN * HH];
__device__ float g_agg2[NN * HH];
__device__ float g_A[NN * HH];
__device__ float g_B[NN * HH];
__device__ float g_C[NN * HH];
__device__ float g_mean[BB * HH];
__device__ float g_var[BB * HH];
__device__ float g_cnt[BB];

// ---------------- zero scratch ----------------
__global__ void zero_kernel() {
    int idx = blockIdx.x * blockDim.x + threadIdx.x;
    if (idx < NN * HH) { g_agg1[idx] = 0.f; g_agg2[idx] = 0.f; }
    if (idx < BB * HH) { g_mean[idx] = 0.f; g_var[idx] = 0.f; }
    if (idx < BB) g_cnt[idx] = 0.f;
}

// ---------------- generic node GEMM: out = op(A1@W1^T [+ A2@W2^T] + bias [+ resid]) ----
// K = 128, Ncols = 128. Block: 256 threads, 64 rows. Micro-tile 8 rows x 4 cols.
constexpr int RB = 64;
constexpr int GEMM_SMEM = (128 * 129 + RB * 128) * 4;

template <bool DUAL, bool SWISH, bool RESID>
__global__ __launch_bounds__(256) void gemm_node(
    const float* __restrict__ A1, const float* __restrict__ W1, int ldw1,
    const float* __restrict__ A2, const float* __restrict__ W2, int ldw2,
    const float* __restrict__ bias, const float* __restrict__ resid,
    float* __restrict__ out, int nrows)
{
    extern __shared__ float sm[];
    float* Ws = sm;               // [128][129] transposed weights
    float* Xs = sm + 128 * 129;   // [RB][128]

    const int tid  = threadIdx.x;
    const int lane = tid & 31;
    const int warp = tid >> 5;
    const int r0   = blockIdx.x * RB;

    float acc[8][4];
#pragma unroll
    for (int i = 0; i < 8; i++)
#pragma unroll
        for (int j = 0; j < 4; j++) acc[i][j] = 0.f;

    const int npass = DUAL ? 2 : 1;
    for (int pass = 0; pass < npass; pass++) {
        const float* A = (pass == 0) ? A1 : A2;
        const float* W = (pass == 0) ? W1 : W2;
        const int ldw  = (pass == 0) ? ldw1 : ldw2;
        if (pass == 1) __syncthreads();
        // load X tile (coalesced)
        for (int i = tid; i < RB * 128; i += 256) {
            int r = r0 + (i >> 7);
            Xs[i] = (r < nrows) ? A[(size_t)r * 128 + (i & 127)] : 0.f;
        }
        // load W transposed: Ws[k*129+c] = W[c*ldw+k] (read coalesced, write conflict-free)
        for (int i = tid; i < 128 * 128; i += 256) {
            int c = i >> 7, k = i & 127;
            Ws[k * 129 + c] = W[(size_t)c * ldw + k];
        }
        __syncthreads();
#pragma unroll 4
        for (int k = 0; k < 128; k++) {
            const float* wr = Ws + k * 129 + lane;
            float w0 = wr[0], w1 = wr[32], w2 = wr[64], w3 = wr[96];
            const float* xr = Xs + (warp << 3) * 128 + k;
#pragma unroll
            for (int i = 0; i < 8; i++) {
                float xv = xr[i * 128];
                acc[i][0] += xv * w0;
                acc[i][1] += xv * w1;
                acc[i][2] += xv * w2;
                acc[i][3] += xv * w3;
            }
        }
    }
    // epilogue
#pragma unroll
    for (int i = 0; i < 8; i++) {
        int r = r0 + (warp << 3) + i;
        if (r < nrows) {
#pragma unroll
            for (int j = 0; j < 4; j++) {
                int c = lane + 32 * j;
                float v = acc[i][j] + bias[c];
                if (SWISH) v = v / (1.f + __expf(-v));
                if (RESID) v += resid[(size_t)r * 128 + c];
                out[(size_t)r * 128 + c] = v;
            }
        }
    }
}

// ---------------- fused edge kernel ----------------
// Per edge: m1 = feat1@W1a^T (64), f1 = m1@W2a^T (128), agg1[dst] += f1 * xact[src]
// and the same for the feat2 path. Grid-stride over 16-edge tiles; 256 threads.
// Warps 0-3 own f1 output channels; warps 4-7 own f2 output channels (W2 rows in regs).
constexpr int EB = 16;

__global__ __launch_bounds__(256, 2) void edge_kernel(
    const float* __restrict__ feat1, const float* __restrict__ feat2,
    const int* __restrict__ ei,
    const float* __restrict__ W1a, const float* __restrict__ W2a,
    const float* __restrict__ W1b, const float* __restrict__ W2b,
    const float* __restrict__ xact,
    float* __restrict__ agg1, float* __restrict__ agg2, int nE)
{
    __shared__ float f1s[EB * IN1];
    __shared__ float f2s[EB * IN2];
    __shared__ __align__(16) float m1s[EB * MID];
    __shared__ __align__(16) float m2s[EB * MID];
    __shared__ float xs[EB * HH];
    __shared__ int sidx[2 * EB];
    __shared__ float Ws1a[IN1 * MID];   // [j][k]
    __shared__ float Ws1b[IN2 * MID];

    const int tid = threadIdx.x;

    // preload first-layer weights transposed into smem
    for (int i = tid; i < MID * IN1; i += 256) { int k = i / IN1, j = i - k * IN1; Ws1a[j * MID + k] = W1a[i]; }
    for (int i = tid; i < MID * IN2; i += 256) { int k = i / IN2, j = i - k * IN2; Ws1b[j * MID + k] = W1b[i]; }

    // preload second-layer weight row into registers: thread h holds W2[h][0..63]
    float w2[MID];
    {
        const float* W2 = (tid < 128) ? W2a : W2b;
        int h = tid & 127;
#pragma unroll
        for (int k = 0; k < MID; k++) w2[k] = W2[h * MID + k];
    }
    __syncthreads();

    const int ntiles = nE / EB;   // E = 1M, divisible by 16
    for (int t = blockIdx.x; t < ntiles; t += gridDim.x) {
        const int e0 = t * EB;
        for (int i = tid; i < EB * IN1; i += 256) f1s[i] = feat1[(size_t)e0 * IN1 + i];
        for (int i = tid; i < EB * IN2; i += 256) f2s[i] = feat2[(size_t)e0 * IN2 + i];
        if (tid < EB) { sidx[tid] = ei[e0 + tid]; sidx[EB + tid] = ei[nE + e0 + tid]; }
        __syncthreads();

        // gather x rows (L2-resident, coalesced 512B rows)
        for (int i = tid; i < EB * HH; i += 256) {
            int e = i >> 7;
            xs[i] = xact[(size_t)sidx[e] * HH + (i & 127)];
        }

        // phase A: m = feat @ W1^T. thread = k + 64*g handles edges g, g+4, g+8, g+12
        {
            const int k = tid & 63, g = tid >> 6;
            float a0 = 0.f, a1 = 0.f, a2 = 0.f, a3 = 0.f;
#pragma unroll 2
            for (int j = 0; j < IN1; j++) {
                float w = Ws1a[j * MID + k];
                a0 += f1s[(g + 0) * IN1 + j] * w;
                a1 += f1s[(g + 4) * IN1 + j] * w;
                a2 += f1s[(g + 8) * IN1 + j] * w;
                a3 += f1s[(g + 12) * IN1 + j] * w;
            }
            m1s[(g + 0) * MID + k] = a0;
            m1s[(g + 4) * MID + k] = a1;
            m1s[(g + 8) * MID + k] = a2;
            m1s[(g + 12) * MID + k] = a3;
            a0 = a1 = a2 = a3 = 0.f;
#pragma unroll 2
            for (int j = 0; j < IN2; j++) {
                float w = Ws1b[j * MID + k];
                a0 += f2s[(g + 0) * IN2 + j] * w;
                a1 += f2s[(g + 4) * IN2 + j] * w;
                a2 += f2s[(g + 8) * IN2 + j] * w;
                a3 += f2s[(g + 12) * IN2 + j] * w;
            }
            m2s[(g + 0) * MID + k] = a0;
            m2s[(g + 4) * MID + k] = a1;
            m2s[(g + 8) * MID + k] = a2;
            m2s[(g + 12) * MID + k] = a3;
        }
        __syncthreads();

        // phase B+C: f_h = m . w2[h]; scatter f_h * x[src][h] into agg[dst][h]
        {
            const int h = tid & 127;
            const float4* msrc = (const float4*)((tid < 128) ? m1s : m2s);
            float* agg = (tid < 128) ? agg1 : agg2;
            for (int e = 0; e < EB; e++) {
                const float4* m4 = msrc + e * (MID / 4);
                float acc = 0.f;
#pragma unroll
                for (int kk = 0; kk < MID / 4; kk++) {
                    float4 m = m4[kk];
                    acc += m.x * w2[4 * kk + 0];
                    acc += m.y * w2[4 * kk + 1];
                    acc += m.z * w2[4 * kk + 2];
                    acc += m.w * w2[4 * kk + 3];
                }
                float v = acc * xs[e * HH + h];
                atomicAdd(agg + (size_t)sidx[EB + e] * HH + h, v);
            }
        }
        __syncthreads();
    }
}

// ---------------- GraphNorm ----------------
__global__ void norm_sum(const float* __restrict__ hin, const int* __restrict__ batch) {
    int idx = blockIdx.x * blockDim.x + threadIdx.x;
    if (idx >= NN * HH) return;
    int n = idx >> 7, h = idx & 127;
    int b = batch[n];
    atomicAdd(&g_mean[b * HH + h], hin[idx]);
    if (h == 0) atomicAdd(&g_cnt[b], 1.f);
}

__global__ void norm_div_mean() {
    int idx = blockIdx.x * blockDim.x + threadIdx.x;
    if (idx >= BB * HH) return;
    g_mean[idx] /= fmaxf(g_cnt[idx >> 7], 1.f);
}

__global__ void norm_center(const float* __restrict__ hin, const int* __restrict__ batch,
                            const float* __restrict__ ms, float* __restrict__ hc_out) {
    int idx = blockIdx.x * blockDim.x + threadIdx.x;
    if (idx >= NN * HH) return;
    int n = idx >> 7, h = idx & 127;
    int b = batch[n];
    float hc = hin[idx] - g_mean[b * HH + h] * ms[h];
    hc_out[idx] = hc;
    atomicAdd(&g_var[b * HH + h], hc * hc);
}

__global__ void norm_div_var() {
    int idx = blockIdx.x * blockDim.x + threadIdx.x;
    if (idx >= BB * HH) return;
    g_var[idx] /= fmaxf(g_cnt[idx >> 7], 1.f);
}

__global__ void norm_apply(const float* __restrict__ hc, const int* __restrict__ batch,
                           const float* __restrict__ w, const float* __restrict__ b_,
                           float* __restrict__ out) {
    int idx = blockIdx.x * blockDim.x + threadIdx.x;
    if (idx >= NN * HH) return;
    int n = idx >> 7, h = idx & 127;
    int b = batch[n];
    out[idx] = w[h] * hc[idx] * rsqrtf(g_var[b * HH + h] + 1e-5f) + b_[h];
}

// ---------------- launch ----------------
extern "C" void kernel_launch(void* const* d_in, const int* in_sizes, int n_in,
                              void* d_out, int out_size)
{
    const float* x        = (const float*)d_in[0];
    const float* feature1 = (const float*)d_in[1];
    const float* feature2 = (const float*)d_in[2];
    const int*   ei       = (const int*)d_in[3];
    const int*   batch    = (const int*)d_in[4];
    const float* lin_W    = (const float*)d_in[5];
    const float* lin_b    = (const float*)d_in[6];
    const float* f1_W1    = (const float*)d_in[7];
    const float* f1_W2    = (const float*)d_in[8];
    const float* f2_W1    = (const float*)d_in[9];
    const float* f2_W2    = (const float*)d_in[10];
    const float* c1_rel_W = (const float*)d_in[11];
    const float* c1_rel_b = (const float*)d_in[12];
    const float* c1_rt_W  = (const float*)d_in[13];
    const float* c2_rel_W = (const float*)d_in[14];
    const float* c2_rel_b = (const float*)d_in[15];
    const float* c2_rt_W  = (const float*)d_in[16];
    const float* lin1_W   = (const float*)d_in[17];
    const float* lin1_b   = (const float*)d_in[18];
    const float* lin2_W   = (const float*)d_in[19];
    const float* lin2_b   = (const float*)d_in[20];
    const float* cat_W    = (const float*)d_in[21];
    const float* cat_b    = (const float*)d_in[22];
    const float* norm_w   = (const float*)d_in[23];
    const float* norm_b   = (const float*)d_in[24];
    const float* norm_ms  = (const float*)d_in[25];
    const float* lins_W   = (const float*)d_in[26];
    const float* lins_b   = (const float*)d_in[27];
    const float* final_W  = (const float*)d_in[28];
    const float* final_b  = (const float*)d_in[29];

    const int nN = in_sizes[0] / HH;
    const int nE = in_sizes[3] / 2;

    float *pxact, *pagg1, *pagg2, *pA, *pB, *pC;
    cudaGetSymbolAddress((void**)&pxact, g_xact);
    cudaGetSymbolAddress((void**)&pagg1, g_agg1);
    cudaGetSymbolAddress((void**)&pagg2, g_agg2);
    cudaGetSymbolAddress((void**)&pA, g_A);
    cudaGetSymbolAddress((void**)&pB, g_B);
    cudaGetSymbolAddress((void**)&pC, g_C);

    cudaFuncSetAttribute(gemm_node<false, true,  false>, cudaFuncAttributeMaxDynamicSharedMemorySize, GEMM_SMEM);
    cudaFuncSetAttribute(gemm_node<true,  false, false>, cudaFuncAttributeMaxDynamicSharedMemorySize, GEMM_SMEM);
    cudaFuncSetAttribute(gemm_node<true,  false, true >, cudaFuncAttributeMaxDynamicSharedMemorySize, GEMM_SMEM);
    cudaFuncSetAttribute(gemm_node<false, true,  true >, cudaFuncAttributeMaxDynamicSharedMemorySize, GEMM_SMEM);
    cudaFuncSetAttribute(gemm_node<false, false, false>, cudaFuncAttributeMaxDynamicSharedMemorySize, GEMM_SMEM);

    const int gblocks = (nN + RB - 1) / RB;

    // 0) zero scratch accumulators
    zero_kernel<<<(NN * HH + 255) / 256, 256>>>();

    // 1) x_act = swish(x @ lin_W^T + lin_b)
    gemm_node<false, true, false><<<gblocks, 256, GEMM_SMEM>>>(
        x, lin_W, HH, nullptr, nullptr, 0, lin_b, nullptr, pxact, nN);

    // 2) fused edge MLP + gather + scatter-add (both paths)
    edge_kernel<<<444, 256>>>(feature1, feature2, ei,
                              f1_W1, f1_W2, f2_W1, f2_W2,
                              pxact, pagg1, pagg2, nE);

    // 3) t1 = agg1@rel1^T + rel1_b + xact@root1^T   -> A
    gemm_node<true, false, false><<<gblocks, 256, GEMM_SMEM>>>(
        pagg1, c1_rel_W, HH, pxact, c1_rt_W, HH, c1_rel_b, nullptr, pA, nN);
    // 4) h1 = swish(t1@lin1^T + lin1_b)             -> B
    gemm_node<false, true, false><<<gblocks, 256, GEMM_SMEM>>>(
        pA, lin1_W, HH, nullptr, nullptr, 0, lin1_b, nullptr, pB, nN);
    // 5) t2 -> A
    gemm_node<true, false, false><<<gblocks, 256, GEMM_SMEM>>>(
        pagg2, c2_rel_W, HH, pxact, c2_rt_W, HH, c2_rel_b, nullptr, pA, nN);
    // 6) h2 = swish(t2@lin2^T + lin2_b)             -> C
    gemm_node<false, true, false><<<gblocks, 256, GEMM_SMEM>>>(
        pA, lin2_W, HH, nullptr, nullptr, 0, lin2_b, nullptr, pC, nN);
    // 7) h = h1@catW[:, :128]^T + h2@catW[:, 128:]^T + cat_b + xact   -> A
    gemm_node<true, false, true><<<gblocks, 256, GEMM_SMEM>>>(
        pB, cat_W, 2 * HH, pC, cat_W + HH, 2 * HH, cat_b, pxact, pA, nN);
    // 8) three residual swish layers: A->B->A->B
    gemm_node<false, true, true><<<gblocks, 256, GEMM_SMEM>>>(
        pA, lins_W + 0 * HH * HH, HH, nullptr, nullptr, 0, lins_b + 0 * HH, pA, pB, nN);
    gemm_node<false, true, true><<<gblocks, 256, GEMM_SMEM>>>(
        pB, lins_W + 1 * HH * HH, HH, nullptr, nullptr, 0, lins_b + 1 * HH, pB, pA, nN);
    gemm_node<false, true, true><<<gblocks, 256, GEMM_SMEM>>>(
        pA, lins_W + 2 * HH * HH, HH, nullptr, nullptr, 0, lins_b + 2 * HH, pA, pB, nN);

    // 9) GraphNorm on B: hc -> C, normalized -> A
    const int nhb = (NN * HH + 255) / 256;
    const int bhb = (BB * HH + 255) / 256;
    norm_sum<<<nhb, 256>>>(pB, batch);
    norm_div_mean<<<bhb, 256>>>();
    norm_center<<<nhb, 256>>>(pB, batch, norm_ms, pC);
    norm_div_var<<<bhb, 256>>>();
    norm_apply<<<nhb, 256>>>(pC, batch, norm_w, norm_b, pA);

    // 10) out = A @ final_W^T + final_b
    gemm_node<false, false, false><<<gblocks, 256, GEMM_SMEM>>>(
        pA, final_W, HH, nullptr, nullptr, 0, final_b, nullptr, (float*)d_out, nN);
}

// round 3
// speedup vs baseline: 1.3788x; 1.3788x over previous
#include <cuda_runtime.h>
#include <cuda_bf16.h>

#define NN 50000
#define EE 1000000
#define BB 512
#define HH 128
#define MID 64
#define IN1 54
#define IN2 18

typedef unsigned long long u64;

#define FMA2(d, a, b, c) asm("fma.rn.f32x2 %0, %1, %2, %3;" : "=l"(d) : "l"(a), "l"(b), "l"(c))

__device__ __forceinline__ u64 pack2(float lo, float hi) {
    u64 r; asm("mov.b64 %0, {%1, %2};" : "=l"(r) : "f"(lo), "f"(hi)); return r;
}
__device__ __forceinline__ void unpack2(u64 v, float& lo, float& hi) {
    asm("mov.b64 {%0, %1}, %2;" : "=f"(lo), "=f"(hi) : "l"(v));
}

// ---------------- scratch (no allocation allowed) ----------------
__device__ float g_xact[NN * HH];
__device__ float g_agg1[NN * HH];
__device__ float g_agg2[NN * HH];
__device__ float g_A[NN * HH];
__device__ float g_B[NN * HH];
__device__ float g_C[NN * HH];
__device__ float g_mean[BB * HH];
__device__ float g_var[BB * HH];
__device__ float g_cnt[BB];

// ---------------- zero scratch ----------------
__global__ void zero_kernel() {
    int idx = blockIdx.x * blockDim.x + threadIdx.x;
    if (idx < NN * HH) { g_agg1[idx] = 0.f; g_agg2[idx] = 0.f; }
    if (idx < BB * HH) { g_mean[idx] = 0.f; g_var[idx] = 0.f; }
    if (idx < BB) g_cnt[idx] = 0.f;
}

// ---------------- node GEMM with packed f32x2 ----------------
// out = op(A1@W1^T [+ A2@W2^T] + bias [+ resid]); K = 128, 128 cols.
// Block: 256 threads, 64 rows. Thread: 8 rows x 4 cols (2 column-pairs).
constexpr int RB = 64;
constexpr int WPAD = 130;                       // even pad: aligned float2, ~2-way conflicts
constexpr int GEMM_SMEM = (128 * WPAD + RB * 128) * 4;

template <bool DUAL, bool SWISH, bool RESID>
__global__ __launch_bounds__(256) void gemm_node(
    const float* __restrict__ A1, const float* __restrict__ W1, int ldw1,
    const float* __restrict__ A2, const float* __restrict__ W2, int ldw2,
    const float* __restrict__ bias, const float* __restrict__ resid,
    float* __restrict__ out, int nrows)
{
    extern __shared__ float sm[];
    float* Ws = sm;                 // [128][WPAD], Ws[k][c] = W[c][k]
    float* Xs = sm + 128 * WPAD;    // [RB][128]

    const int tid  = threadIdx.x;
    const int lane = tid & 31;
    const int warp = tid >> 5;
    const int r0   = blockIdx.x * RB;

    u64 acc[8][2];
#pragma unroll
    for (int i = 0; i < 8; i++) { acc[i][0] = 0ull; acc[i][1] = 0ull; }

    const int npass = DUAL ? 2 : 1;
    for (int pass = 0; pass < npass; pass++) {
        const float* A = (pass == 0) ? A1 : A2;
        const float* W = (pass == 0) ? W1 : W2;
        const int ldw  = (pass == 0) ? ldw1 : ldw2;
        if (pass == 1) __syncthreads();
        // load X tile (coalesced)
        for (int i = tid; i < RB * 128; i += 256) {
            int r = r0 + (i >> 7);
            Xs[i] = (r < nrows) ? A[(size_t)r * 128 + (i & 127)] : 0.f;
        }
        // load W transposed: Ws[k*WPAD+c] = W[c*ldw+k]
        for (int i = tid; i < 128 * 128; i += 256) {
            int c = i >> 7, k = i & 127;
            Ws[k * WPAD + c] = W[(size_t)c * ldw + k];
        }
        __syncthreads();
#pragma unroll 2
        for (int k = 0; k < 128; k++) {
            float2 w0 = *(const float2*)(Ws + k * WPAD + 2 * lane);
            float2 w1 = *(const float2*)(Ws + k * WPAD + 64 + 2 * lane);
            u64 w0p = pack2(w0.x, w0.y);
            u64 w1p = pack2(w1.x, w1.y);
            const float* xr = Xs + (warp << 3) * 128 + k;
#pragma unroll
            for (int i = 0; i < 8; i++) {
                float xv = xr[i * 128];
                u64 x2 = pack2(xv, xv);
                FMA2(acc[i][0], x2, w0p, acc[i][0]);
                FMA2(acc[i][1], x2, w1p, acc[i][1]);
            }
        }
    }
    // epilogue: thread owns cols (2*lane, 2*lane+1) and (64+2*lane, 65+2*lane)
    float2 b0 = *(const float2*)(bias + 2 * lane);
    float2 b1 = *(const float2*)(bias + 64 + 2 * lane);
#pragma unroll
    for (int i = 0; i < 8; i++) {
        int r = r0 + (warp << 3) + i;
        if (r < nrows) {
            float v0, v1, v2, v3;
            unpack2(acc[i][0], v0, v1);
            unpack2(acc[i][1], v2, v3);
            v0 += b0.x; v1 += b0.y; v2 += b1.x; v3 += b1.y;
            if (SWISH) {
                v0 = v0 / (1.f + __expf(-v0));
                v1 = v1 / (1.f + __expf(-v1));
                v2 = v2 / (1.f + __expf(-v2));
                v3 = v3 / (1.f + __expf(-v3));
            }
            float* orow = out + (size_t)r * 128;
            if (RESID) {
                const float* rr = resid + (size_t)r * 128;
                float2 r0v = *(const float2*)(rr + 2 * lane);
                float2 r1v = *(const float2*)(rr + 64 + 2 * lane);
                v0 += r0v.x; v1 += r0v.y; v2 += r1v.x; v3 += r1v.y;
            }
            *(float2*)(orow + 2 * lane)      = make_float2(v0, v1);
            *(float2*)(orow + 64 + 2 * lane) = make_float2(v2, v3);
        }
    }
}

// ---------------- fused edge kernel (f32x2) ----------------
constexpr int EB = 16;

__global__ __launch_bounds__(256, 2) void edge_kernel(
    const float* __restrict__ feat1, const float* __restrict__ feat2,
    const int* __restrict__ ei,
    const float* __restrict__ W1a, const float* __restrict__ W2a,
    const float* __restrict__ W1b, const float* __restrict__ W2b,
    const float* __restrict__ xact,
    float* __restrict__ agg1, float* __restrict__ agg2, int nE)
{
    __shared__ __align__(16) float f1s[EB * IN1];
    __shared__ __align__(16) float f2s[EB * IN2];
    __shared__ __align__(16) float m1s[EB * MID];
    __shared__ __align__(16) float m2s[EB * MID];
    __shared__ __align__(16) float xs[EB * HH];
    __shared__ int sidx[2 * EB];
    __shared__ __align__(16) float Ws1a[MID * IN1];  // identity copy: [k][j]
    __shared__ __align__(16) float Ws1b[MID * IN2];

    const int tid = threadIdx.x;

    // preload first-layer weights (row-major [k][j], j-pairs contiguous)
    for (int i = tid; i < MID * IN1; i += 256) Ws1a[i] = W1a[i];
    for (int i = tid; i < MID * IN2; i += 256) Ws1b[i] = W1b[i];

    // preload second-layer weight row packed: thread h holds W2[h][0..63] as 32 u64 pairs
    u64 w2p[MID / 2];
    {
        const u64* w2g = (const u64*)(((tid < 128) ? W2a : W2b) + (size_t)(tid & 127) * MID);
#pragma unroll
        for (int kk = 0; kk < MID / 2; kk++) w2p[kk] = w2g[kk];
    }
    __syncthreads();

    const int ntiles = nE / EB;   // E = 1M, divisible by 16
    for (int t = blockIdx.x; t < ntiles; t += gridDim.x) {
        const int e0 = t * EB;
        for (int i = tid; i < EB * IN1; i += 256) f1s[i] = feat1[(size_t)e0 * IN1 + i];
        for (int i = tid; i < EB * IN2; i += 256) f2s[i] = feat2[(size_t)e0 * IN2 + i];
        if (tid < EB) { sidx[tid] = ei[e0 + tid]; sidx[EB + tid] = ei[nE + e0 + tid]; }
        __syncthreads();

        // gather x rows (L2-resident)
        for (int i = tid; i < EB * HH; i += 256) {
            int e = i >> 7;
            xs[i] = xact[(size_t)sidx[e] * HH + (i & 127)];
        }

        // phase A: m = feat @ W1^T, packed over j-pairs.
        // thread = (k, g): k = tid&63, edges g, g+4, g+8, g+12
        {
            const int k = tid & 63, g = tid >> 6;
            {
                const u64* wrow = (const u64*)(Ws1a + k * IN1);
                const u64* fr0 = (const u64*)(f1s + (g + 0)  * IN1);
                const u64* fr1 = (const u64*)(f1s + (g + 4)  * IN1);
                const u64* fr2 = (const u64*)(f1s + (g + 8)  * IN1);
                const u64* fr3 = (const u64*)(f1s + (g + 12) * IN1);
                u64 a0 = 0ull, a1 = 0ull, a2 = 0ull, a3 = 0ull;
#pragma unroll
                for (int jp = 0; jp < IN1 / 2; jp++) {
                    u64 w = wrow[jp];
                    FMA2(a0, fr0[jp], w, a0);
                    FMA2(a1, fr1[jp], w, a1);
                    FMA2(a2, fr2[jp], w, a2);
                    FMA2(a3, fr3[jp], w, a3);
                }
                float lo, hi;
                unpack2(a0, lo, hi); m1s[(g + 0)  * MID + k] = lo + hi;
                unpack2(a1, lo, hi); m1s[(g + 4)  * MID + k] = lo + hi;
                unpack2(a2, lo, hi); m1s[(g + 8)  * MID + k] = lo + hi;
                unpack2(a3, lo, hi); m1s[(g + 12) * MID + k] = lo + hi;
            }
            {
                const u64* wrow = (const u64*)(Ws1b + k * IN2);
                const u64* fr0 = (const u64*)(f2s + (g + 0)  * IN2);
                const u64* fr1 = (const u64*)(f2s + (g + 4)  * IN2);
                const u64* fr2 = (const u64*)(f2s + (g + 8)  * IN2);
                const u64* fr3 = (const u64*)(f2s + (g + 12) * IN2);
                u64 a0 = 0ull, a1 = 0ull, a2 = 0ull, a3 = 0ull;
#pragma unroll
                for (int jp = 0; jp < IN2 / 2; jp++) {
                    u64 w = wrow[jp];
                    FMA2(a0, fr0[jp], w, a0);
                    FMA2(a1, fr1[jp], w, a1);
                    FMA2(a2, fr2[jp], w, a2);
                    FMA2(a3, fr3[jp], w, a3);
                }
                float lo, hi;
                unpack2(a0, lo, hi); m2s[(g + 0)  * MID + k] = lo + hi;
                unpack2(a1, lo, hi); m2s[(g + 4)  * MID + k] = lo + hi;
                unpack2(a2, lo, hi); m2s[(g + 8)  * MID + k] = lo + hi;
                unpack2(a3, lo, hi); m2s[(g + 12) * MID + k] = lo + hi;
            }
        }
        __syncthreads();

        // phase B+C: f_h = m . w2[h]; scatter f_h * x[src][h] into agg[dst][h]
        {
            const int h = tid & 127;
            const float* msrcf = (tid < 128) ? m1s : m2s;
            float* agg = (tid < 128) ? agg1 : agg2;
#pragma unroll 2
            for (int e = 0; e < EB; e++) {
                const ulonglong2* mp = (const ulonglong2*)(msrcf + e * MID);
                u64 acc0 = 0ull, acc1 = 0ull;
#pragma unroll
                for (int kk = 0; kk < MID / 4; kk++) {
                    ulonglong2 mv = mp[kk];
                    FMA2(acc0, mv.x, w2p[2 * kk + 0], acc0);
                    FMA2(acc1, mv.y, w2p[2 * kk + 1], acc1);
                }
                float l0, h0, l1, h1;
                unpack2(acc0, l0, h0);
                unpack2(acc1, l1, h1);
                float v = ((l0 + l1) + (h0 + h1)) * xs[e * HH + h];
                atomicAdd(agg + (size_t)sidx[EB + e] * HH + h, v);
            }
        }
        __syncthreads();
    }
}

// ---------------- GraphNorm ----------------
__global__ void norm_sum(const float* __restrict__ hin, const int* __restrict__ batch) {
    int idx = blockIdx.x * blockDim.x + threadIdx.x;
    if (idx >= NN * HH) return;
    int n = idx >> 7, h = idx & 127;
    int b = batch[n];
    atomicAdd(&g_mean[b * HH + h], hin[idx]);
    if (h == 0) atomicAdd(&g_cnt[b], 1.f);
}

__global__ void norm_center(const float* __restrict__ hin, const int* __restrict__ batch,
                            const float* __restrict__ ms, float* __restrict__ hc_out) {
    int idx = blockIdx.x * blockDim.x + threadIdx.x;
    if (idx >= NN * HH) return;
    int n = idx >> 7, h = idx & 127;
    int b = batch[n];
    float cnt = fmaxf(g_cnt[b], 1.f);
    float mean = g_mean[b * HH + h] / cnt;
    float hc = hin[idx] - mean * ms[h];
    hc_out[idx] = hc;
    atomicAdd(&g_var[b * HH + h], hc * hc);
}

__global__ void norm_apply(const float* __restrict__ hc, const int* __restrict__ batch,
                           const float* __restrict__ w, const float* __restrict__ b_,
                           float* __restrict__ out) {
    int idx = blockIdx.x * blockDim.x + threadIdx.x;
    if (idx >= NN * HH) return;
    int n = idx >> 7, h = idx & 127;
    int b = batch[n];
    float cnt = fmaxf(g_cnt[b], 1.f);
    float var = g_var[b * HH + h] / cnt;
    out[idx] = w[h] * hc[idx] * rsqrtf(var + 1e-5f) + b_[h];
}

// ---------------- launch ----------------
extern "C" void kernel_launch(void* const* d_in, const int* in_sizes, int n_in,
                              void* d_out, int out_size)
{
    const float* x        = (const float*)d_in[0];
    const float* feature1 = (const float*)d_in[1];
    const float* feature2 = (const float*)d_in[2];
    const int*   ei       = (const int*)d_in[3];
    const int*   batch    = (const int*)d_in[4];
    const float* lin_W    = (const float*)d_in[5];
    const float* lin_b    = (const float*)d_in[6];
    const float* f1_W1    = (const float*)d_in[7];
    const float* f1_W2    = (const float*)d_in[8];
    const float* f2_W1    = (const float*)d_in[9];
    const float* f2_W2    = (const float*)d_in[10];
    const float* c1_rel_W = (const float*)d_in[11];
    const float* c1_rel_b = (const float*)d_in[12];
    const float* c1_rt_W  = (const float*)d_in[13];
    const float* c2_rel_W = (const float*)d_in[14];
    const float* c2_rel_b = (const float*)d_in[15];
    const float* c2_rt_W  = (const float*)d_in[16];
    const float* lin1_W   = (const float*)d_in[17];
    const float* lin1_b   = (const float*)d_in[18];
    const float* lin2_W   = (const float*)d_in[19];
    const float* lin2_b   = (const float*)d_in[20];
    const float* cat_W    = (const float*)d_in[21];
    const float* cat_b    = (const float*)d_in[22];
    const float* norm_w   = (const float*)d_in[23];
    const float* norm_b   = (const float*)d_in[24];
    const float* norm_ms  = (const float*)d_in[25];
    const float* lins_W   = (const float*)d_in[26];
    const float* lins_b   = (const float*)d_in[27];
    const float* final_W  = (const float*)d_in[28];
    const float* final_b  = (const float*)d_in[29];

    const int nN = in_sizes[0] / HH;
    const int nE = in_sizes[3] / 2;

    float *pxact, *pagg1, *pagg2, *pA, *pB, *pC;
    cudaGetSymbolAddress((void**)&pxact, g_xact);
    cudaGetSymbolAddress((void**)&pagg1, g_agg1);
    cudaGetSymbolAddress((void**)&pagg2, g_agg2);
    cudaGetSymbolAddress((void**)&pA, g_A);
    cudaGetSymbolAddress((void**)&pB, g_B);
    cudaGetSymbolAddress((void**)&pC, g_C);

    cudaFuncSetAttribute(gemm_node<false, true,  false>, cudaFuncAttributeMaxDynamicSharedMemorySize, GEMM_SMEM);
    cudaFuncSetAttribute(gemm_node<true,  false, false>, cudaFuncAttributeMaxDynamicSharedMemorySize, GEMM_SMEM);
    cudaFuncSetAttribute(gemm_node<true,  false, true >, cudaFuncAttributeMaxDynamicSharedMemorySize, GEMM_SMEM);
    cudaFuncSetAttribute(gemm_node<false, true,  true >, cudaFuncAttributeMaxDynamicSharedMemorySize, GEMM_SMEM);
    cudaFuncSetAttribute(gemm_node<false, false, false>, cudaFuncAttributeMaxDynamicSharedMemorySize, GEMM_SMEM);

    const int gblocks = (nN + RB - 1) / RB;

    // 0) zero scratch accumulators
    zero_kernel<<<(NN * HH + 255) / 256, 256>>>();

    // 1) x_act = swish(x @ lin_W^T + lin_b)
    gemm_node<false, true, false><<<gblocks, 256, GEMM_SMEM>>>(
        x, lin_W, HH, nullptr, nullptr, 0, lin_b, nullptr, pxact, nN);

    // 2) fused edge MLP + gather + scatter-add (both paths)
    edge_kernel<<<296, 256>>>(feature1, feature2, ei,
                              f1_W1, f1_W2, f2_W1, f2_W2,
                              pxact, pagg1, pagg2, nE);

    // 3) t1 = agg1@rel1^T + rel1_b + xact@root1^T   -> A
    gemm_node<true, false, false><<<gblocks, 256, GEMM_SMEM>>>(
        pagg1, c1_rel_W, HH, pxact, c1_rt_W, HH, c1_rel_b, nullptr, pA, nN);
    // 4) h1 = swish(t1@lin1^T + lin1_b)             -> B
    gemm_node<false, true, false><<<gblocks, 256, GEMM_SMEM>>>(
        pA, lin1_W, HH, nullptr, nullptr, 0, lin1_b, nullptr, pB, nN);
    // 5) t2 -> A
    gemm_node<true, false, false><<<gblocks, 256, GEMM_SMEM>>>(
        pagg2, c2_rel_W, HH, pxact, c2_rt_W, HH, c2_rel_b, nullptr, pA, nN);
    // 6) h2 = swish(t2@lin2^T + lin2_b)             -> C
    gemm_node<false, true, false><<<gblocks, 256, GEMM_SMEM>>>(
        pA, lin2_W, HH, nullptr, nullptr, 0, lin2_b, nullptr, pC, nN);
    // 7) h = h1@catW[:, :128]^T + h2@catW[:, 128:]^T + cat_b + xact   -> A
    gemm_node<true, false, true><<<gblocks, 256, GEMM_SMEM>>>(
        pB, cat_W, 2 * HH, pC, cat_W + HH, 2 * HH, cat_b, pxact, pA, nN);
    // 8) three residual swish layers
    gemm_node<false, true, true><<<gblocks, 256, GEMM_SMEM>>>(
        pA, lins_W + 0 * HH * HH, HH, nullptr, nullptr, 0, lins_b + 0 * HH, pA, pB, nN);
    gemm_node<false, true, true><<<gblocks, 256, GEMM_SMEM>>>(
        pB, lins_W + 1 * HH * HH, HH, nullptr, nullptr, 0, lins_b + 1 * HH, pB, pA, nN);
    gemm_node<false, true, true><<<gblocks, 256, GEMM_SMEM>>>(
        pA, lins_W + 2 * HH * HH, HH, nullptr, nullptr, 0, lins_b + 2 * HH, pA, pB, nN);

    // 9) GraphNorm on B: hc -> C, normalized -> A
    const int nhb = (NN * HH + 255) / 256;
    norm_sum<<<nhb, 256>>>(pB, batch);
    norm_center<<<nhb, 256>>>(pB, batch, norm_ms, pC);
    norm_apply<<<nhb, 256>>>(pC, batch, norm_w, norm_b, pA);

    // 10) out = A @ final_W^T + final_b
    gemm_node<false, false, false><<<gblocks, 256, GEMM_SMEM>>>(
        pA, final_W, HH, nullptr, nullptr, 0, final_b, nullptr, (float*)d_out, nN);
}